// round 14
// baseline (speedup 1.0000x reference)
#include <cuda_runtime.h>
#include <cuda_fp16.h>
#include <cstdint>

#define TPB     512
#define TILE_M  32
#define STATE   24
#define L1D     100
#define L2D     100
#define NHEAD   27
#define ACT     6

#define NT12    13
#define NT3     4
#define KS1     2
#define KS23    7

#define S1_32   36
#define LO1     16
#define S2_32   116
#define LO2     56

// ---- smem layout (b32 word offsets) ----
#define F_BP1   0
#define F_BP2   (F_BP1 + KS1*NT12*32*4)         //  3328
#define F_BP3   (F_BP2 + KS23*NT12*32*4)        // 14976
#define F_BH    (F_BP3 + KS23*NT3*32*4)         // 18560 (32 fp32 head biases)
#define F_PIPE  (F_BH + 32)                     // 18592
#define P_AS1   0
#define P_AS2   (TILE_M*S1_32)                  // 1152
#define P_ST    (P_AS2 + TILE_M*S2_32)          // 4864  (double-buffered out staging)
#define ST_W    (TILE_M*36 + TILE_M*ACT)        // 1344 words per buffer
#define P_PART  (P_ST + 2*ST_W)                 // 7552  (head split-K partials, 1024 w)
#define PIPE_W  (P_PART + 1024)                 // 8576
#define F_TOTAL (F_PIPE + 4*PIPE_W)             // 52896 words = 211584 B

__constant__ int c_pos[21]   = {0,6,7,12,13,14,18,19,20,21,24,25,26,27,28,30,31,32,33,34,35};
__constant__ int c_upper[15] = {1,2,3,4,5,8,9,10,11,15,16,17,22,23,29};

__device__ __forceinline__ uint32_t packh(__half a, __half b) {
    return (uint32_t)__half_as_ushort(a) | ((uint32_t)__half_as_ushort(b) << 16);
}
__device__ __forceinline__ void split2(float v0, float v1, uint32_t& hi, uint32_t& lo) {
    __half h0 = __float2half_rn(v0), h1 = __float2half_rn(v1);
    __half l0 = __float2half_rn(v0 - __half2float(h0));
    __half l1 = __float2half_rn(v1 - __half2float(h1));
    hi = packh(h0, h1); lo = packh(l0, l1);
}

__device__ __forceinline__ void mma16(float* c, const uint32_t* a, uint32_t b0, uint32_t b1) {
    asm volatile("mma.sync.aligned.m16n8k16.row.col.f32.f16.f16.f32 "
                 "{%0,%1,%2,%3},{%4,%5,%6,%7},{%8,%9},{%0,%1,%2,%3};"
                 : "+f"(c[0]), "+f"(c[1]), "+f"(c[2]), "+f"(c[3])
                 : "r"(a[0]), "r"(a[1]), "r"(a[2]), "r"(a[3]), "r"(b0), "r"(b1));
}

__device__ __forceinline__ void ldsm_x4(uint32_t (&r)[4], uint32_t saddr) {
    asm volatile("ldmatrix.sync.aligned.m8n8.x4.shared.b16 {%0,%1,%2,%3}, [%4];"
                 : "=r"(r[0]), "=r"(r[1]), "=r"(r[2]), "=r"(r[3]) : "r"(saddr));
}

#define PIPE_BAR() asm volatile("bar.sync %0, 128;" :: "r"(1 + pipe) : "memory")

extern __shared__ uint32_t smem[];

// 3-term f16 warp GEMM; 16 rows per warp, A fragments via ldmatrix.x4.
template<int KS, int NTW>
__device__ __forceinline__ void wgemm_ldsm(const uint32_t* __restrict__ A32, int S32v, int LO,
                                           const uint4* __restrict__ Bp,
                                           int NTT, int nt0, int cnt,
                                           int wrow, int lane,
                                           float (&c)[NTW][4])
{
    #pragma unroll
    for (int j = 0; j < NTW; j++)
        #pragma unroll
        for (int i = 0; i < 4; i++) c[j][i] = 0.0f;

    const uint32_t abase = (uint32_t)__cvta_generic_to_shared(A32)
                         + ((uint32_t)((wrow + (lane & 15)) * S32v + (lane >> 4) * 4)) * 4u;

    #pragma unroll 1
    for (int ks = 0; ks < KS; ks++) {
        uint4 bfr[NTW];
        #pragma unroll
        for (int j = 0; j < NTW; j++)
            if (j < cnt) bfr[j] = Bp[(ks * NTT + nt0 + j) * 32 + lane];

        uint32_t ah[4], al[4];
        {
            const uint32_t ad = abase + (uint32_t)(ks * 32);
            ldsm_x4(ah, ad);
            ldsm_x4(al, ad + (uint32_t)(LO * 4));
        }

        #pragma unroll
        for (int term = 0; term < 3; term++)
            #pragma unroll
            for (int j = 0; j < NTW; j++) {
                if (j >= cnt) continue;
                uint32_t b0 = (term == 2) ? bfr[j].z : bfr[j].x;
                uint32_t b1 = (term == 2) ? bfr[j].w : bfr[j].y;
                mma16(c[j], (term == 1) ? al : ah, b0, b1);
            }
    }
}

// layer-1 epilogue: relu + split + STS into As2 planes
template<int NTW>
__device__ __forceinline__ void epi_relu16(float (&c)[NTW][4], uint32_t* A2,
                                           int wrow, int nt0, int cnt, int g, int t)
{
    const int row = wrow + g;
    #pragma unroll
    for (int j = 0; j < NTW; j++) {
        if (j >= cnt) continue;
        const int nt = nt0 + j;
        if (nt == 12 && t >= 2) continue;
        const int pi = 4 * nt + t;
        uint32_t h, l;
        split2(fmaxf(c[j][0], 0.f), fmaxf(c[j][1], 0.f), h, l);
        A2[row * S2_32 + pi] = h;  A2[row * S2_32 + LO2 + pi] = l;
        split2(fmaxf(c[j][2], 0.f), fmaxf(c[j][3], 0.f), h, l);
        A2[(row + 8) * S2_32 + pi] = h;  A2[(row + 8) * S2_32 + LO2 + pi] = l;
    }
}

__global__ void __launch_bounds__(TPB, 1)
actor_mma(const float* __restrict__ states,
          const float* __restrict__ W1, const float* __restrict__ b1,
          const float* __restrict__ W2, const float* __restrict__ b2,
          const float* __restrict__ Wm, const float* __restrict__ bm,
          const float* __restrict__ Wc, const float* __restrict__ bc,
          float* __restrict__ out, int B)
{
    const int tid  = threadIdx.x;
    const int lane = tid & 31;
    const int wid  = tid >> 5;
    const int g    = lane >> 2;
    const int t    = lane & 3;

    const int pipe  = wid >> 2;       // 0..3 — one warp per SMSP per pipeline
    const int w     = wid & 3;
    const int ptid  = tid & 127;
    const int nhalf = w >> 1;

    // layers 1,2 (M=32): M2 x N2 (balanced 7/6)
    const int wrow = (w & 1) * 16;
    const int nt0  = nhalf * 7;
    const int ncnt = nhalf ? 6 : 7;

    uint32_t* pb   = smem + F_PIPE + pipe * PIPE_W;
    uint32_t* As1  = pb + P_AS1;
    uint32_t* As2  = pb + P_AS2;
    float*    bh_s = reinterpret_cast<float*>(smem + F_BH);
    const uint4* Bp1 = reinterpret_cast<const uint4*>(smem + F_BP1);
    const uint4* Bp2 = reinterpret_cast<const uint4*>(smem + F_BP2);
    const uint4* Bp3 = reinterpret_cast<const uint4*>(smem + F_BP3);

    // ---- stage packed f16 hi/lo weight fragments (biases folded as K-column) ----
    for (int i = tid; i < KS1 * NT12 * 32; i += TPB) {
        int ln = i & 31, slot = i >> 5, ks = slot / NT12, nt = slot - ks * NT12;
        int n = (ln >> 2) + 8 * nt, k0 = 16 * ks + 2 * (ln & 3);
        float wv[4];
        #pragma unroll
        for (int q = 0; q < 4; q++) {
            int k = k0 + (q >> 1) * 8 + (q & 1);
            wv[q] = (n < L1D) ? (k < STATE ? W1[n * STATE + k] : (k == STATE ? b1[n] : 0.f)) : 0.f;
        }
        uint4 fr; uint32_t lo0, lo1;
        split2(wv[0], wv[1], fr.x, lo0); split2(wv[2], wv[3], fr.y, lo1);
        fr.z = lo0; fr.w = lo1;
        reinterpret_cast<uint4*>(smem + F_BP1)[i] = fr;
    }
    for (int i = tid; i < KS23 * NT12 * 32; i += TPB) {
        int ln = i & 31, slot = i >> 5, ks = slot / NT12, nt = slot - ks * NT12;
        int n = (ln >> 2) + 8 * nt, k0 = 16 * ks + 2 * (ln & 3);
        float wv[4];
        #pragma unroll
        for (int q = 0; q < 4; q++) {
            int k = k0 + (q >> 1) * 8 + (q & 1);
            wv[q] = (n < L2D) ? (k < L1D ? W2[n * L1D + k] : (k == L1D ? b2[n] : 0.f)) : 0.f;
        }
        uint4 fr; uint32_t lo0, lo1;
        split2(wv[0], wv[1], fr.x, lo0); split2(wv[2], wv[3], fr.y, lo1);
        fr.z = lo0; fr.w = lo1;
        reinterpret_cast<uint4*>(smem + F_BP2)[i] = fr;
    }
    // head weights: NO bias column (bias added exactly in epilogue)
    for (int i = tid; i < KS23 * NT3 * 32; i += TPB) {
        int ln = i & 31, slot = i >> 5, ks = slot / NT3, nt = slot - ks * NT3;
        int n = (ln >> 2) + 8 * nt, k0 = 16 * ks + 2 * (ln & 3);
        float wv[4];
        #pragma unroll
        for (int q = 0; q < 4; q++) {
            int k = k0 + (q >> 1) * 8 + (q & 1);
            float v = 0.f;
            if (k < L2D) {
                if (n < ACT)        v = Wm[n * L2D + k];
                else if (n < NHEAD) v = Wc[(n - ACT) * L2D + k];
            }
            wv[q] = v;
        }
        uint4 fr; uint32_t lo0, lo1;
        split2(wv[0], wv[1], fr.x, lo0); split2(wv[2], wv[3], fr.y, lo1);
        fr.z = lo0; fr.w = lo1;
        reinterpret_cast<uint4*>(smem + F_BP3)[i] = fr;
    }
    if (tid < 32)
        bh_s[tid] = (tid < ACT) ? bm[tid] : (tid < NHEAD ? bc[tid - ACT] : 0.f);
    // one-time per-pipeline activation pad init
    for (int i = ptid; i < TILE_M * S2_32; i += 128) As2[i] = 0u;
    __syncthreads();
    if (ptid < TILE_M) {
        const uint32_t one = packh(__float2half_rn(1.f), __ushort_as_half(0));
        As2[ptid * S2_32 + 50] = one;                 // bias col 100 (layer 2)
        uint32_t* rr = As1 + ptid * S1_32;
        rr[12] = one;  rr[LO1 + 12] = 0u;             // bias col 24 (layer 1)
        #pragma unroll
        for (int p = 13; p < 16; p++) { rr[p] = 0u; rr[LO1 + p] = 0u; }
    }
    __syncthreads();

    const int ntiles = (B + TILE_M - 1) / TILE_M;
    const int stride = gridDim.x * 4;
    const int tile0  = blockIdx.x * 4 + pipe;

    // ---- pre-loop: load + write X(tile0), prefetch X(tile0+stride) ----
    float4 px0, px1, px2;
    if (ptid < 2 * TILE_M && tile0 < ntiles) {
        long m = (long)tile0 * TILE_M + (ptid >> 1); if (m >= B) m = B - 1;
        const float4* src = reinterpret_cast<const float4*>(states + m * STATE) + (ptid & 1) * 3;
        px0 = src[0]; px1 = src[1]; px2 = src[2];
        const int row = ptid >> 1, half = ptid & 1;
        uint32_t* rh = As1 + row * S1_32 + half * 6;
        uint32_t h, l;
        split2(px0.x, px0.y, h, l); rh[0] = h; rh[LO1 + 0] = l;
        split2(px0.z, px0.w, h, l); rh[1] = h; rh[LO1 + 1] = l;
        split2(px1.x, px1.y, h, l); rh[2] = h; rh[LO1 + 2] = l;
        split2(px1.z, px1.w, h, l); rh[3] = h; rh[LO1 + 3] = l;
        split2(px2.x, px2.y, h, l); rh[4] = h; rh[LO1 + 4] = l;
        split2(px2.z, px2.w, h, l); rh[5] = h; rh[LO1 + 5] = l;
    }
    PIPE_BAR();
    if (ptid < 2 * TILE_M && tile0 + stride < ntiles) {
        long m = (long)(tile0 + stride) * TILE_M + (ptid >> 1); if (m >= B) m = B - 1;
        const float4* src = reinterpret_cast<const float4*>(states + m * STATE) + (ptid & 1) * 3;
        px0 = src[0]; px1 = src[1]; px2 = src[2];
    }

    int buf = 0;
    for (int tile = tile0; tile < ntiles; tile += stride) {
        float* sChol = reinterpret_cast<float*>(pb + P_ST + buf * ST_W);
        float* sMean = sChol + TILE_M * 36;
        float4* part = reinterpret_cast<float4*>(pb + P_PART) + (w & 1) * 128;

        // ---- layer 1: As1 -> As2 ----
        {
            float c1[7][4];
            wgemm_ldsm<KS1, 7>(As1, S1_32, LO1, Bp1, NT12, nt0, ncnt, wrow, lane, c1);
            epi_relu16<7>(c1, As2, wrow, nt0, ncnt, g, t);
        }
        PIPE_BAR();                                        // S2: hidden1 ready, As1 free

        // ---- write next X into As1 (overlaps layer-2), prefetch next-next ----
        {
            int nxt = tile + stride;
            if (ptid < 2 * TILE_M && nxt < ntiles) {
                const int row = ptid >> 1, half = ptid & 1;
                uint32_t* rh = As1 + row * S1_32 + half * 6;
                uint32_t h, l;
                split2(px0.x, px0.y, h, l); rh[0] = h; rh[LO1 + 0] = l;
                split2(px0.z, px0.w, h, l); rh[1] = h; rh[LO1 + 1] = l;
                split2(px1.x, px1.y, h, l); rh[2] = h; rh[LO1 + 2] = l;
                split2(px1.z, px1.w, h, l); rh[3] = h; rh[LO1 + 3] = l;
                split2(px2.x, px2.y, h, l); rh[4] = h; rh[LO1 + 4] = l;
                split2(px2.z, px2.w, h, l); rh[5] = h; rh[LO1 + 5] = l;
            }
            int nxt2 = tile + 2 * stride;
            if (ptid < 2 * TILE_M && nxt2 < ntiles) {
                long m = (long)nxt2 * TILE_M + (ptid >> 1); if (m >= B) m = B - 1;
                const float4* src = reinterpret_cast<const float4*>(states + m * STATE) + (ptid & 1) * 3;
                px0 = src[0]; px1 = src[1]; px2 = src[2];
            }
        }

        // ---- layer 2: As2 -> registers (relu + hi/lo split, no STS) ----
        uint32_t ph[7][2], pl[7][2];
        {
            float c2[7][4];
            wgemm_ldsm<KS23, 7>(As2, S2_32, LO2, Bp2, NT12, nt0, ncnt, wrow, lane, c2);
            #pragma unroll
            for (int j = 0; j < 7; j++) {
                split2(fmaxf(c2[j][0], 0.f), fmaxf(c2[j][1], 0.f), ph[j][0], pl[j][0]);
                split2(fmaxf(c2[j][2], 0.f), fmaxf(c2[j][3], 0.f), ph[j][1], pl[j][1]);
            }
            // (j >= ncnt entries are zero: wgemm left those c2 at 0)
        }

        // ---- head: split-K GEMM from registers (n0: blocks 0-6, n1: blocks 7-12) ----
        float c3[4][4];
        #pragma unroll
        for (int nt = 0; nt < 4; nt++)
            #pragma unroll
            for (int i = 0; i < 4; i++) c3[nt][i] = 0.0f;

        #pragma unroll
        for (int s = 0; s < 4; s++) {
            const int ks = nhalf ? (3 + s) : s;
            uint32_t AH[4], AL[4];
            if (nhalf == 0) {
                const int j0 = 2 * s;
                AH[0] = ph[j0][0]; AH[1] = ph[j0][1];
                AL[0] = pl[j0][0]; AL[1] = pl[j0][1];
                if (s < 3) {
                    AH[2] = ph[j0+1][0]; AH[3] = ph[j0+1][1];
                    AL[2] = pl[j0+1][0]; AL[3] = pl[j0+1][1];
                } else { AH[2]=AH[3]=AL[2]=AL[3]=0u; }
            } else {
                if (s > 0) {
                    const int ja = 2 * s - 1;
                    AH[0] = ph[ja][0]; AH[1] = ph[ja][1];
                    AL[0] = pl[ja][0]; AL[1] = pl[ja][1];
                } else { AH[0]=AH[1]=AL[0]=AL[1]=0u; }
                if (s < 3) {
                    const int jb = 2 * s;
                    AH[2] = ph[jb][0]; AH[3] = ph[jb][1];
                    AL[2] = pl[jb][0]; AL[3] = pl[jb][1];
                } else { AH[2]=AH[3]=AL[2]=AL[3]=0u; }
            }
            uint4 bfr[4];
            #pragma unroll
            for (int nt = 0; nt < 4; nt++) bfr[nt] = Bp3[(ks * NT3 + nt) * 32 + lane];
            #pragma unroll
            for (int term = 0; term < 3; term++)
                #pragma unroll
                for (int nt = 0; nt < 4; nt++) {
                    uint32_t b0 = (term == 2) ? bfr[nt].z : bfr[nt].x;
                    uint32_t b1 = (term == 2) ? bfr[nt].w : bfr[nt].y;
                    mma16(c3[nt], (term == 1) ? AL : AH, b0, b1);
                }
        }

        // ---- split-K reduction: store the 2 nt the partner scatters ----
        {
            const int ob = nhalf ? 0 : 2;
            part[(ob + 0) * 32 + lane] = make_float4(c3[ob][0],   c3[ob][1],   c3[ob][2],   c3[ob][3]);
            part[(ob + 1) * 32 + lane] = make_float4(c3[ob+1][0], c3[ob+1][1], c3[ob+1][2], c3[ob+1][3]);
        }
        PIPE_BAR();                                        // S-reduce (also: As2 reads done)

        // ---- reduce + bias + activations + staged scatter ----
        {
            const int sb = nhalf ? 2 : 0;
            #pragma unroll
            for (int jj = 0; jj < 2; jj++) {
                float4 p = part[(sb + jj) * 32 + lane];
                float vv[4] = { c3[sb+jj][0] + p.x, c3[sb+jj][1] + p.y,
                                c3[sb+jj][2] + p.z, c3[sb+jj][3] + p.w };
                #pragma unroll
                for (int i = 0; i < 4; i++) {
                    int row = wrow + g + ((i >= 2) ? 8 : 0);
                    int col = 8 * (sb + jj) + 2 * t + (i & 1);
                    float v = vv[i] + bh_s[col];
                    if (col < ACT) {
                        sMean[row * ACT + col] = tanhf(v);
                    } else if (col < NHEAD) {
                        float sp = fmaxf(v, 0.f) + log1pf(expf(-fabsf(v)));
                        sChol[row * 36 + c_pos[col - ACT]] = sp;
                    }
                }
            }
            if (ptid < TILE_M) {
                #pragma unroll
                for (int j = 0; j < 15; j++) sChol[ptid * 36 + c_upper[j]] = 0.0f;
            }
        }
        PIPE_BAR();                                        // S5: staged

        // ---- coalesced writeback (double-buffered staging, no trailing bar) ----
        if ((tile + 1) * TILE_M <= B) {
            float4* pm = reinterpret_cast<float4*>(out + (size_t)tile * (TILE_M * ACT));
            const float4* sm4 = reinterpret_cast<const float4*>(sMean);
            for (int i = ptid; i < TILE_M * ACT / 4; i += 128) pm[i] = sm4[i];
            float4* pc = reinterpret_cast<float4*>(out + (size_t)B * ACT + (size_t)tile * (TILE_M * 36));
            const float4* sc4 = reinterpret_cast<const float4*>(sChol);
            for (int i = ptid; i < TILE_M * 36 / 4; i += 128) pc[i] = sc4[i];
        } else {
            int nrow = B - tile * TILE_M;
            for (int i = ptid; i < nrow * ACT; i += 128)
                out[(size_t)tile * (TILE_M * ACT) + i] = sMean[i];
            for (int i = ptid; i < nrow * 36; i += 128)
                out[(size_t)B * ACT + (size_t)tile * (TILE_M * 36) + i] = sChol[i];
        }
        buf ^= 1;
    }
}

extern "C" void kernel_launch(void* const* d_in, const int* in_sizes, int n_in,
                              void* d_out, int out_size)
{
    const float* states = (const float*)d_in[0];
    const float* W1 = (const float*)d_in[1];
    const float* b1 = (const float*)d_in[2];
    const float* W2 = (const float*)d_in[3];
    const float* b2 = (const float*)d_in[4];
    const float* Wm = (const float*)d_in[5];
    const float* bm = (const float*)d_in[6];
    const float* Wc = (const float*)d_in[7];
    const float* bc = (const float*)d_in[8];
    float* out = (float*)d_out;

    const int B = in_sizes[0] / STATE;
    const int ntiles = (B + TILE_M - 1) / TILE_M;
    const size_t smem_bytes = (size_t)F_TOTAL * 4;   // 211584 B

    cudaFuncSetAttribute(actor_mma,
                         cudaFuncAttributeMaxDynamicSharedMemorySize,
                         (int)smem_bytes);

    int nstreams = (ntiles + 3) / 4;
    int grid = nstreams < 152 ? nstreams : 152;      // 1 CTA/SM, 4 pipelines each
    actor_mma<<<grid, TPB, smem_bytes>>>(states, W1, b1, W2, b2,
                                         Wm, bm, Wc, bc, out, B);
}

// round 15
// speedup vs baseline: 1.0696x; 1.0696x over previous
#include <cuda_runtime.h>
#include <cuda_fp16.h>
#include <cstdint>

#define TPB     512
#define TILE_M  32
#define STATE   24
#define L1D     100
#define L2D     100
#define NHEAD   27
#define ACT     6

#define NT12    13
#define NT3     4
#define KS1     2
#define KS23    7

#define S1_32   36
#define LO1     16
#define S2_32   116
#define LO2     56

// ---- smem layout (b32 word offsets) ----
#define F_BP1   0
#define F_BP2   (F_BP1 + KS1*NT12*32*4)         //  3328
#define F_BP3   (F_BP2 + KS23*NT12*32*4)        // 14976
#define F_PIPE  (F_BP3 + KS23*NT3*32*4)         // 18560
#define P_AS1   0
#define P_AS2   (TILE_M*S1_32)                  // 1152
#define P_ST    (P_AS2 + TILE_M*S2_32)          // 4864  (double-buffered staging)
#define ST_W    (TILE_M*36 + TILE_M*ACT)        // 1344 words per buffer
#define PIPE_W  (P_ST + 2*ST_W)                 // 7552 words
#define F_TOTAL (F_PIPE + 4*PIPE_W)             // 48768 words = 195072 B

__constant__ int c_pos[21]   = {0,6,7,12,13,14,18,19,20,21,24,25,26,27,28,30,31,32,33,34,35};

__device__ __forceinline__ uint32_t packh(__half a, __half b) {
    return (uint32_t)__half_as_ushort(a) | ((uint32_t)__half_as_ushort(b) << 16);
}
__device__ __forceinline__ void split2(float v0, float v1, uint32_t& hi, uint32_t& lo) {
    __half h0 = __float2half_rn(v0), h1 = __float2half_rn(v1);
    __half l0 = __float2half_rn(v0 - __half2float(h0));
    __half l1 = __float2half_rn(v1 - __half2float(h1));
    hi = packh(h0, h1); lo = packh(l0, l1);
}

__device__ __forceinline__ void mma16(float* c, const uint32_t* a, uint32_t b0, uint32_t b1) {
    asm volatile("mma.sync.aligned.m16n8k16.row.col.f32.f16.f16.f32 "
                 "{%0,%1,%2,%3},{%4,%5,%6,%7},{%8,%9},{%0,%1,%2,%3};"
                 : "+f"(c[0]), "+f"(c[1]), "+f"(c[2]), "+f"(c[3])
                 : "r"(a[0]), "r"(a[1]), "r"(a[2]), "r"(a[3]), "r"(b0), "r"(b1));
}

__device__ __forceinline__ void ldsm_x4(uint32_t (&r)[4], uint32_t saddr) {
    asm volatile("ldmatrix.sync.aligned.m8n8.x4.shared.b16 {%0,%1,%2,%3}, [%4];"
                 : "=r"(r[0]), "=r"(r[1]), "=r"(r[2]), "=r"(r[3]) : "r"(saddr));
}

#define PIPE_BAR() asm volatile("bar.sync %0, 128;" :: "r"(1 + pipe) : "memory")

extern __shared__ uint32_t smem[];

// 3-term f16 warp GEMM; 16 rows per warp (MT=1), A fragments via ldmatrix.x4.
template<int KS, int NTW>
__device__ __forceinline__ void wgemm_ldsm(const uint32_t* __restrict__ A32, int S32v, int LO,
                                           const uint4* __restrict__ Bp,
                                           int NTT, int nt0, int cnt,
                                           int wrow, int lane,
                                           float (&c)[NTW][4])
{
    #pragma unroll
    for (int j = 0; j < NTW; j++)
        #pragma unroll
        for (int i = 0; i < 4; i++) c[j][i] = 0.0f;

    const uint32_t abase = (uint32_t)__cvta_generic_to_shared(A32)
                         + ((uint32_t)((wrow + (lane & 15)) * S32v + (lane >> 4) * 4)) * 4u;

    #pragma unroll 1
    for (int ks = 0; ks < KS; ks++) {
        uint4 bfr[NTW];
        #pragma unroll
        for (int j = 0; j < NTW; j++)
            if (j < cnt) bfr[j] = Bp[(ks * NTT + nt0 + j) * 32 + lane];

        uint32_t ah[4], al[4];
        {
            const uint32_t ad = abase + (uint32_t)(ks * 32);
            ldsm_x4(ah, ad);
            ldsm_x4(al, ad + (uint32_t)(LO * 4));
        }

        #pragma unroll
        for (int term = 0; term < 3; term++)
            #pragma unroll
            for (int j = 0; j < NTW; j++) {
                if (j >= cnt) continue;
                uint32_t b0 = (term == 2) ? bfr[j].z : bfr[j].x;
                uint32_t b1 = (term == 2) ? bfr[j].w : bfr[j].y;
                mma16(c[j], (term == 1) ? al : ah, b0, b1);
            }
    }
}

template<int NTW>
__device__ __forceinline__ void epi_relu16(float (&c)[NTW][4], uint32_t* A2,
                                           int wrow, int nt0, int cnt, int g, int t)
{
    const int row = wrow + g;
    #pragma unroll
    for (int j = 0; j < NTW; j++) {
        if (j >= cnt) continue;
        const int nt = nt0 + j;
        if (nt == 12 && t >= 2) continue;      // cols >= 100
        const int pi = 4 * nt + t;
        uint32_t h, l;
        split2(fmaxf(c[j][0], 0.f), fmaxf(c[j][1], 0.f), h, l);
        A2[row * S2_32 + pi] = h;  A2[row * S2_32 + LO2 + pi] = l;
        split2(fmaxf(c[j][2], 0.f), fmaxf(c[j][3], 0.f), h, l);
        A2[(row + 8) * S2_32 + pi] = h;  A2[(row + 8) * S2_32 + LO2 + pi] = l;
    }
}

__global__ void __launch_bounds__(TPB, 1)
actor_mma(const float* __restrict__ states,
          const float* __restrict__ W1, const float* __restrict__ b1,
          const float* __restrict__ W2, const float* __restrict__ b2,
          const float* __restrict__ Wm, const float* __restrict__ bm,
          const float* __restrict__ Wc, const float* __restrict__ bc,
          float* __restrict__ out, int B)
{
    const int tid  = threadIdx.x;
    const int lane = tid & 31;
    const int wid  = tid >> 5;
    const int g    = lane >> 2;
    const int t    = lane & 3;

    const int pipe = wid >> 2;        // 0..3 — one warp per SMSP per pipeline
    const int w    = wid & 3;
    const int ptid = tid & 127;

    // layers 1,2 (M=32): M2 x N2 (balanced 7/6)
    const int wrow = (w & 1) * 16;
    const int nt0  = (w >> 1) * 7;
    const int ncnt = (w >> 1) ? 6 : 7;
    // head (M=32, N=32): M2 x N2
    const int wrow3 = (w & 1) * 16;
    const int nt03  = (w >> 1) * 2;

    uint32_t* pb   = smem + F_PIPE + pipe * PIPE_W;
    uint32_t* As1  = pb + P_AS1;
    uint32_t* As2  = pb + P_AS2;
    const uint4* Bp1 = reinterpret_cast<const uint4*>(smem + F_BP1);
    const uint4* Bp2 = reinterpret_cast<const uint4*>(smem + F_BP2);
    const uint4* Bp3 = reinterpret_cast<const uint4*>(smem + F_BP3);

    // ---- stage packed f16 hi/lo weight fragments (biases folded as K-column) ----
    for (int i = tid; i < KS1 * NT12 * 32; i += TPB) {
        int ln = i & 31, slot = i >> 5, ks = slot / NT12, nt = slot - ks * NT12;
        int n = (ln >> 2) + 8 * nt, k0 = 16 * ks + 2 * (ln & 3);
        float wv[4];
        #pragma unroll
        for (int q = 0; q < 4; q++) {
            int k = k0 + (q >> 1) * 8 + (q & 1);
            wv[q] = (n < L1D) ? (k < STATE ? W1[n * STATE + k] : (k == STATE ? b1[n] : 0.f)) : 0.f;
        }
        uint4 fr; uint32_t lo0, lo1;
        split2(wv[0], wv[1], fr.x, lo0); split2(wv[2], wv[3], fr.y, lo1);
        fr.z = lo0; fr.w = lo1;
        reinterpret_cast<uint4*>(smem + F_BP1)[i] = fr;
    }
    for (int i = tid; i < KS23 * NT12 * 32; i += TPB) {
        int ln = i & 31, slot = i >> 5, ks = slot / NT12, nt = slot - ks * NT12;
        int n = (ln >> 2) + 8 * nt, k0 = 16 * ks + 2 * (ln & 3);
        float wv[4];
        #pragma unroll
        for (int q = 0; q < 4; q++) {
            int k = k0 + (q >> 1) * 8 + (q & 1);
            wv[q] = (n < L2D) ? (k < L1D ? W2[n * L1D + k] : (k == L1D ? b2[n] : 0.f)) : 0.f;
        }
        uint4 fr; uint32_t lo0, lo1;
        split2(wv[0], wv[1], fr.x, lo0); split2(wv[2], wv[3], fr.y, lo1);
        fr.z = lo0; fr.w = lo1;
        reinterpret_cast<uint4*>(smem + F_BP2)[i] = fr;
    }
    for (int i = tid; i < KS23 * NT3 * 32; i += TPB) {
        int ln = i & 31, slot = i >> 5, ks = slot / NT3, nt = slot - ks * NT3;
        int n = (ln >> 2) + 8 * nt, k0 = 16 * ks + 2 * (ln & 3);
        float wv[4];
        #pragma unroll
        for (int q = 0; q < 4; q++) {
            int k = k0 + (q >> 1) * 8 + (q & 1);
            float v = 0.f;
            if (n < ACT)        v = k < L2D ? Wm[n * L2D + k] : (k == L2D ? bm[n] : 0.f);
            else if (n < NHEAD) v = k < L2D ? Wc[(n - ACT) * L2D + k] : (k == L2D ? bc[n - ACT] : 0.f);
            wv[q] = v;
        }
        uint4 fr; uint32_t lo0, lo1;
        split2(wv[0], wv[1], fr.x, lo0); split2(wv[2], wv[3], fr.y, lo1);
        fr.z = lo0; fr.w = lo1;
        reinterpret_cast<uint4*>(smem + F_BP3)[i] = fr;
    }
    // one-time activation pad init + ZERO BOTH STAGING BUFFERS ONCE
    // (chol upper-triangle positions are never written by the scatter, so a
    //  single pre-zero serves every tile; removes 15 STS/thread/tile)
    for (int i = ptid; i < TILE_M * S2_32; i += 128) As2[i] = 0u;
    for (int i = ptid; i < 2 * ST_W; i += 128) pb[P_ST + i] = 0u;
    __syncthreads();
    if (ptid < TILE_M) {
        const uint32_t one = packh(__float2half_rn(1.f), __ushort_as_half(0));
        As2[ptid * S2_32 + 50] = one;                 // bias col 100
        uint32_t* rr = As1 + ptid * S1_32;
        rr[12] = one;  rr[LO1 + 12] = 0u;             // bias col 24
        #pragma unroll
        for (int p = 13; p < 16; p++) { rr[p] = 0u; rr[LO1 + p] = 0u; }
    }
    __syncthreads();

    const int ntiles = (B + TILE_M - 1) / TILE_M;
    const int stride = gridDim.x * 4;
    const int tile0  = blockIdx.x * 4 + pipe;

    // ---- pre-loop: load + write X(tile0), then prefetch X(tile0+stride) ----
    float4 px0, px1, px2;
    if (ptid < 2 * TILE_M && tile0 < ntiles) {
        long m = (long)tile0 * TILE_M + (ptid >> 1); if (m >= B) m = B - 1;
        const float4* src = reinterpret_cast<const float4*>(states + m * STATE) + (ptid & 1) * 3;
        px0 = src[0]; px1 = src[1]; px2 = src[2];
        const int row = ptid >> 1, half = ptid & 1;
        uint32_t* rh = As1 + row * S1_32 + half * 6;
        uint32_t h, l;
        split2(px0.x, px0.y, h, l); rh[0] = h; rh[LO1 + 0] = l;
        split2(px0.z, px0.w, h, l); rh[1] = h; rh[LO1 + 1] = l;
        split2(px1.x, px1.y, h, l); rh[2] = h; rh[LO1 + 2] = l;
        split2(px1.z, px1.w, h, l); rh[3] = h; rh[LO1 + 3] = l;
        split2(px2.x, px2.y, h, l); rh[4] = h; rh[LO1 + 4] = l;
        split2(px2.z, px2.w, h, l); rh[5] = h; rh[LO1 + 5] = l;
    }
    PIPE_BAR();
    if (ptid < 2 * TILE_M && tile0 + stride < ntiles) {
        long m = (long)(tile0 + stride) * TILE_M + (ptid >> 1); if (m >= B) m = B - 1;
        const float4* src = reinterpret_cast<const float4*>(states + m * STATE) + (ptid & 1) * 3;
        px0 = src[0]; px1 = src[1]; px2 = src[2];
    }

    int buf = 0;
    for (int tile = tile0; tile < ntiles; tile += stride) {
        float* sChol = reinterpret_cast<float*>(pb + P_ST + buf * ST_W);
        float* sMean = sChol + TILE_M * 36;

        // ---- layer 1: As1 -> As2 ----
        {
            float c1[7][4];
            wgemm_ldsm<KS1, 7>(As1, S1_32, LO1, Bp1, NT12, nt0, ncnt, wrow, lane, c1);
            epi_relu16<7>(c1, As2, wrow, nt0, ncnt, g, t);
        }
        PIPE_BAR();                                        // S2: hidden1 ready + As1 reads done

        // ---- write next tile's X into As1 (overlaps layer-2 phase), prefetch next-next ----
        {
            int nxt = tile + stride;
            if (ptid < 2 * TILE_M && nxt < ntiles) {
                const int row = ptid >> 1, half = ptid & 1;
                uint32_t* rh = As1 + row * S1_32 + half * 6;
                uint32_t h, l;
                split2(px0.x, px0.y, h, l); rh[0] = h; rh[LO1 + 0] = l;
                split2(px0.z, px0.w, h, l); rh[1] = h; rh[LO1 + 1] = l;
                split2(px1.x, px1.y, h, l); rh[2] = h; rh[LO1 + 2] = l;
                split2(px1.z, px1.w, h, l); rh[3] = h; rh[LO1 + 3] = l;
                split2(px2.x, px2.y, h, l); rh[4] = h; rh[LO1 + 4] = l;
                split2(px2.z, px2.w, h, l); rh[5] = h; rh[LO1 + 5] = l;
            }
            int nxt2 = tile + 2 * stride;
            if (ptid < 2 * TILE_M && nxt2 < ntiles) {
                long m = (long)nxt2 * TILE_M + (ptid >> 1); if (m >= B) m = B - 1;
                const float4* src = reinterpret_cast<const float4*>(states + m * STATE) + (ptid & 1) * 3;
                px0 = src[0]; px1 = src[1]; px2 = src[2];
            }
        }

        // ---- layer 2: As2 -> As2 ----
        {
            float c2[7][4];
            wgemm_ldsm<KS23, 7>(As2, S2_32, LO2, Bp2, NT12, nt0, ncnt, wrow, lane, c2);
            PIPE_BAR();                                    // S3: As2 reads done
            epi_relu16<7>(c2, As2, wrow, nt0, ncnt, g, t);
        }
        PIPE_BAR();                                        // S4: hidden2 ready

        // ---- head gemm + staged activation scatter (buffer `buf`) ----
        {
            float c3[2][4];
            wgemm_ldsm<KS23, 2>(As2, S2_32, LO2, Bp3, NT3, nt03, 2, wrow3, lane, c3);
            #pragma unroll
            for (int j = 0; j < 2; j++)
                #pragma unroll
                for (int i = 0; i < 4; i++) {
                    int row = wrow3 + g + ((i >= 2) ? 8 : 0);
                    int col = 8 * (nt03 + j) + 2 * t + (i & 1);
                    float v = c3[j][i];
                    if (col < ACT) {
                        sMean[row * ACT + col] = tanhf(v);
                    } else if (col < NHEAD) {
                        float sp = fmaxf(v, 0.f) + log1pf(expf(-fabsf(v)));
                        sChol[row * 36 + c_pos[col - ACT]] = sp;
                    }
                }
            // (upper-triangle zeros pre-initialized once; scatter never touches them)
        }
        PIPE_BAR();                                        // S5: staged

        // ---- coalesced writeback (no trailing barrier: next scatter uses buf^1) ----
        if ((tile + 1) * TILE_M <= B) {
            float4* pm = reinterpret_cast<float4*>(out + (size_t)tile * (TILE_M * ACT));
            const float4* sm4 = reinterpret_cast<const float4*>(sMean);
            for (int i = ptid; i < TILE_M * ACT / 4; i += 128) pm[i] = sm4[i];
            float4* pc = reinterpret_cast<float4*>(out + (size_t)B * ACT + (size_t)tile * (TILE_M * 36));
            const float4* sc4 = reinterpret_cast<const float4*>(sChol);
            for (int i = ptid; i < TILE_M * 36 / 4; i += 128) pc[i] = sc4[i];
        } else {
            int nrow = B - tile * TILE_M;
            for (int i = ptid; i < nrow * ACT; i += 128)
                out[(size_t)tile * (TILE_M * ACT) + i] = sMean[i];
            for (int i = ptid; i < nrow * 36; i += 128)
                out[(size_t)B * ACT + (size_t)tile * (TILE_M * 36) + i] = sChol[i];
        }
        buf ^= 1;
    }
}

extern "C" void kernel_launch(void* const* d_in, const int* in_sizes, int n_in,
                              void* d_out, int out_size)
{
    const float* states = (const float*)d_in[0];
    const float* W1 = (const float*)d_in[1];
    const float* b1 = (const float*)d_in[2];
    const float* W2 = (const float*)d_in[3];
    const float* b2 = (const float*)d_in[4];
    const float* Wm = (const float*)d_in[5];
    const float* bm = (const float*)d_in[6];
    const float* Wc = (const float*)d_in[7];
    const float* bc = (const float*)d_in[8];
    float* out = (float*)d_out;

    const int B = in_sizes[0] / STATE;
    const int ntiles = (B + TILE_M - 1) / TILE_M;
    const size_t smem_bytes = (size_t)F_TOTAL * 4;   // 195072 B

    cudaFuncSetAttribute(actor_mma,
                         cudaFuncAttributeMaxDynamicSharedMemorySize,
                         (int)smem_bytes);

    int nstreams = (ntiles + 3) / 4;
    int grid = nstreams < 152 ? nstreams : 152;      // 1 CTA/SM, 4 pipelines each
    actor_mma<<<grid, TPB, smem_bytes>>>(states, W1, b1, W2, b2,
                                         Wm, bm, Wc, bc, out, B);
}

// round 16
// speedup vs baseline: 1.0921x; 1.0211x over previous
#include <cuda_runtime.h>
#include <cuda_fp16.h>
#include <cstdint>

#define TPB     512
#define TILE_M  32
#define STATE   24
#define L1D     100
#define L2D     100
#define NHEAD   27
#define ACT     6

#define NT12    13
#define NT3     4
#define KS1     2
#define KS23    7

#define S1_32   36
#define LO1     16
#define S2_32   116
#define LO2     56

// ---- smem layout (b32 word offsets) ----
#define F_BP1   0
#define F_BP2   (F_BP1 + KS1*NT12*32*4)         //  3328
#define F_BP3   (F_BP2 + KS23*NT12*32*4)        // 14976
#define F_PIPE  (F_BP3 + KS23*NT3*32*4)         // 18560
#define P_AS1   0
#define P_AS2   (TILE_M*S1_32)                  // 1152
#define P_ST    (P_AS2 + TILE_M*S2_32)          // 4864
#define ST_W    (TILE_M*36 + TILE_M*ACT)        // 1344 words per buffer
#define PIPE_W  (P_ST + 2*ST_W)                 // 7552 words
#define F_TOTAL (F_PIPE + 4*PIPE_W)             // 48768 words = 195072 B

__constant__ int c_pos[21]   = {0,6,7,12,13,14,18,19,20,21,24,25,26,27,28,30,31,32,33,34,35};

__device__ __forceinline__ uint32_t packh(__half a, __half b) {
    return (uint32_t)__half_as_ushort(a) | ((uint32_t)__half_as_ushort(b) << 16);
}
__device__ __forceinline__ void split2(float v0, float v1, uint32_t& hi, uint32_t& lo) {
    __half h0 = __float2half_rn(v0), h1 = __float2half_rn(v1);
    __half l0 = __float2half_rn(v0 - __half2float(h0));
    __half l1 = __float2half_rn(v1 - __half2float(h1));
    hi = packh(h0, h1); lo = packh(l0, l1);
}

__device__ __forceinline__ void mma16(float* c, const uint32_t* a, uint32_t b0, uint32_t b1) {
    asm volatile("mma.sync.aligned.m16n8k16.row.col.f32.f16.f16.f32 "
                 "{%0,%1,%2,%3},{%4,%5,%6,%7},{%8,%9},{%0,%1,%2,%3};"
                 : "+f"(c[0]), "+f"(c[1]), "+f"(c[2]), "+f"(c[3])
                 : "r"(a[0]), "r"(a[1]), "r"(a[2]), "r"(a[3]), "r"(b0), "r"(b1));
}

__device__ __forceinline__ void ldsm_x4(uint32_t (&r)[4], uint32_t saddr) {
    asm volatile("ldmatrix.sync.aligned.m8n8.x4.shared.b16 {%0,%1,%2,%3}, [%4];"
                 : "=r"(r[0]), "=r"(r[1]), "=r"(r[2]), "=r"(r[3]) : "r"(saddr));
}

#define PIPE_BAR() asm volatile("bar.sync %0, 128;" :: "r"(1 + pipe) : "memory")

extern __shared__ uint32_t smem[];

// MT1 warp GEMM (layer 1 + head): 16 rows per warp, ldmatrix.x4 A loads.
template<int KS, int NTW>
__device__ __forceinline__ void wgemm_ldsm(const uint32_t* __restrict__ A32, int S32v, int LO,
                                           const uint4* __restrict__ Bp,
                                           int NTT, int nt0, int cnt,
                                           int wrow, int lane,
                                           float (&c)[NTW][4])
{
    #pragma unroll
    for (int j = 0; j < NTW; j++)
        #pragma unroll
        for (int i = 0; i < 4; i++) c[j][i] = 0.0f;

    const uint32_t abase = (uint32_t)__cvta_generic_to_shared(A32)
                         + ((uint32_t)((wrow + (lane & 15)) * S32v + (lane >> 4) * 4)) * 4u;

    #pragma unroll 1
    for (int ks = 0; ks < KS; ks++) {
        uint4 bfr[NTW];
        #pragma unroll
        for (int j = 0; j < NTW; j++)
            if (j < cnt) bfr[j] = Bp[(ks * NTT + nt0 + j) * 32 + lane];

        uint32_t ah[4], al[4];
        {
            const uint32_t ad = abase + (uint32_t)(ks * 32);
            ldsm_x4(ah, ad);
            ldsm_x4(al, ad + (uint32_t)(LO * 4));
        }

        #pragma unroll
        for (int term = 0; term < 3; term++)
            #pragma unroll
            for (int j = 0; j < NTW; j++) {
                if (j >= cnt) continue;
                uint32_t b0 = (term == 2) ? bfr[j].z : bfr[j].x;
                uint32_t b1 = (term == 2) ? bfr[j].w : bfr[j].y;
                mma16(c[j], (term == 1) ? al : ah, b0, b1);
            }
    }
}

// layer-1 epilogue (MT1): relu + split + STS into As2 planes
template<int NTW>
__device__ __forceinline__ void epi_relu16(float (&c)[NTW][4], uint32_t* A2,
                                           int wrow, int nt0, int cnt, int g, int t)
{
    const int row = wrow + g;
    #pragma unroll
    for (int j = 0; j < NTW; j++) {
        if (j >= cnt) continue;
        const int nt = nt0 + j;
        if (nt == 12 && t >= 2) continue;
        const int pi = 4 * nt + t;
        uint32_t h, l;
        split2(fmaxf(c[j][0], 0.f), fmaxf(c[j][1], 0.f), h, l);
        A2[row * S2_32 + pi] = h;  A2[row * S2_32 + LO2 + pi] = l;
        split2(fmaxf(c[j][2], 0.f), fmaxf(c[j][3], 0.f), h, l);
        A2[(row + 8) * S2_32 + pi] = h;  A2[(row + 8) * S2_32 + LO2 + pi] = l;
    }
}

// ---- Layer-2 balanced MT2: each warp covers all 32 rows; per-j masks pick
// which m-halves it owns. mask bit0 = mt0 (rows 0-15), bit1 = mt1 (rows 16-31).
template<int KS, int CNT, int M0, int ML>
__device__ __forceinline__ void wgemm_mt2(const uint32_t* __restrict__ A32, int S32v, int LO,
                                          const uint4* __restrict__ Bp,
                                          int NTT, int nt0, int lane,
                                          float (&c)[4][2][4])
{
    #pragma unroll
    for (int j = 0; j < 4; j++)
        #pragma unroll
        for (int mt = 0; mt < 2; mt++)
            #pragma unroll
            for (int i = 0; i < 4; i++) c[j][mt][i] = 0.0f;

    const uint32_t abase = (uint32_t)__cvta_generic_to_shared(A32)
                         + ((uint32_t)((lane & 15) * S32v + (lane >> 4) * 4)) * 4u;
    const uint32_t astep = (uint32_t)(16 * S32v * 4);

    #pragma unroll 1
    for (int ks = 0; ks < KS; ks++) {
        uint4 bfr[CNT];
        #pragma unroll
        for (int j = 0; j < CNT; j++)
            bfr[j] = Bp[(ks * NTT + nt0 + j) * 32 + lane];

        uint32_t ah[2][4], al[2][4];
        {
            const uint32_t ad = abase + (uint32_t)(ks * 32);
            ldsm_x4(ah[0], ad);
            ldsm_x4(al[0], ad + (uint32_t)(LO * 4));
            ldsm_x4(ah[1], ad + astep);
            ldsm_x4(al[1], ad + astep + (uint32_t)(LO * 4));
        }

        #pragma unroll
        for (int term = 0; term < 3; term++)
            #pragma unroll
            for (int j = 0; j < CNT; j++) {
                const int mask = (j == 0) ? M0 : ((j == CNT - 1) ? ML : 3);
                uint32_t b0 = (term == 2) ? bfr[j].z : bfr[j].x;
                uint32_t b1 = (term == 2) ? bfr[j].w : bfr[j].y;
                #pragma unroll
                for (int mt = 0; mt < 2; mt++)
                    if (mask & (1 << mt))
                        mma16(c[j][mt], (term == 1) ? al[mt] : ah[mt], b0, b1);
            }
    }
}

template<int CNT, int M0, int ML>
__device__ __forceinline__ void epi_mt2(float (&c)[4][2][4], uint32_t* A2,
                                        int nt0, int g, int t)
{
    #pragma unroll
    for (int j = 0; j < CNT; j++) {
        const int nt = nt0 + j;
        if (nt == 12 && t >= 2) continue;      // cols >= 100
        const int mask = (j == 0) ? M0 : ((j == CNT - 1) ? ML : 3);
        const int pi = 4 * nt + t;
        #pragma unroll
        for (int mt = 0; mt < 2; mt++) {
            if (!(mask & (1 << mt))) continue;
            const int row = 16 * mt + g;
            uint32_t h, l;
            split2(fmaxf(c[j][mt][0], 0.f), fmaxf(c[j][mt][1], 0.f), h, l);
            A2[row * S2_32 + pi] = h;  A2[row * S2_32 + LO2 + pi] = l;
            split2(fmaxf(c[j][mt][2], 0.f), fmaxf(c[j][mt][3], 0.f), h, l);
            A2[(row + 8) * S2_32 + pi] = h;  A2[(row + 8) * S2_32 + LO2 + pi] = l;
        }
    }
}

__global__ void __launch_bounds__(TPB, 1)
actor_mma(const float* __restrict__ states,
          const float* __restrict__ W1, const float* __restrict__ b1,
          const float* __restrict__ W2, const float* __restrict__ b2,
          const float* __restrict__ Wm, const float* __restrict__ bm,
          const float* __restrict__ Wc, const float* __restrict__ bc,
          float* __restrict__ out, int B)
{
    const int tid  = threadIdx.x;
    const int lane = tid & 31;
    const int wid  = tid >> 5;
    const int g    = lane >> 2;
    const int t    = lane & 3;

    const int pipe = wid >> 2;        // 0..3 — one warp per SMSP per pipeline
    const int w    = wid & 3;
    const int ptid = tid & 127;

    // layer 1 (M=32): M2 x N2 (balanced 7/6)
    const int wrow = (w & 1) * 16;
    const int nt0  = (w >> 1) * 7;
    const int ncnt = (w >> 1) ? 6 : 7;
    // head (M=32, N=32): M2 x N2
    const int wrow3 = (w & 1) * 16;
    const int nt03  = (w >> 1) * 2;

    uint32_t* pb   = smem + F_PIPE + pipe * PIPE_W;
    uint32_t* As1  = pb + P_AS1;
    uint32_t* As2  = pb + P_AS2;
    const uint4* Bp1 = reinterpret_cast<const uint4*>(smem + F_BP1);
    const uint4* Bp2 = reinterpret_cast<const uint4*>(smem + F_BP2);
    const uint4* Bp3 = reinterpret_cast<const uint4*>(smem + F_BP3);

    // ---- stage packed f16 hi/lo weight fragments (biases folded as K-column) ----
    for (int i = tid; i < KS1 * NT12 * 32; i += TPB) {
        int ln = i & 31, slot = i >> 5, ks = slot / NT12, nt = slot - ks * NT12;
        int n = (ln >> 2) + 8 * nt, k0 = 16 * ks + 2 * (ln & 3);
        float wv[4];
        #pragma unroll
        for (int q = 0; q < 4; q++) {
            int k = k0 + (q >> 1) * 8 + (q & 1);
            wv[q] = (n < L1D) ? (k < STATE ? W1[n * STATE + k] : (k == STATE ? b1[n] : 0.f)) : 0.f;
        }
        uint4 fr; uint32_t lo0, lo1;
        split2(wv[0], wv[1], fr.x, lo0); split2(wv[2], wv[3], fr.y, lo1);
        fr.z = lo0; fr.w = lo1;
        reinterpret_cast<uint4*>(smem + F_BP1)[i] = fr;
    }
    for (int i = tid; i < KS23 * NT12 * 32; i += TPB) {
        int ln = i & 31, slot = i >> 5, ks = slot / NT12, nt = slot - ks * NT12;
        int n = (ln >> 2) + 8 * nt, k0 = 16 * ks + 2 * (ln & 3);
        float wv[4];
        #pragma unroll
        for (int q = 0; q < 4; q++) {
            int k = k0 + (q >> 1) * 8 + (q & 1);
            wv[q] = (n < L2D) ? (k < L1D ? W2[n * L1D + k] : (k == L1D ? b2[n] : 0.f)) : 0.f;
        }
        uint4 fr; uint32_t lo0, lo1;
        split2(wv[0], wv[1], fr.x, lo0); split2(wv[2], wv[3], fr.y, lo1);
        fr.z = lo0; fr.w = lo1;
        reinterpret_cast<uint4*>(smem + F_BP2)[i] = fr;
    }
    for (int i = tid; i < KS23 * NT3 * 32; i += TPB) {
        int ln = i & 31, slot = i >> 5, ks = slot / NT3, nt = slot - ks * NT3;
        int n = (ln >> 2) + 8 * nt, k0 = 16 * ks + 2 * (ln & 3);
        float wv[4];
        #pragma unroll
        for (int q = 0; q < 4; q++) {
            int k = k0 + (q >> 1) * 8 + (q & 1);
            float v = 0.f;
            if (n < ACT)        v = k < L2D ? Wm[n * L2D + k] : (k == L2D ? bm[n] : 0.f);
            else if (n < NHEAD) v = k < L2D ? Wc[(n - ACT) * L2D + k] : (k == L2D ? bc[n - ACT] : 0.f);
            wv[q] = v;
        }
        uint4 fr; uint32_t lo0, lo1;
        split2(wv[0], wv[1], fr.x, lo0); split2(wv[2], wv[3], fr.y, lo1);
        fr.z = lo0; fr.w = lo1;
        reinterpret_cast<uint4*>(smem + F_BP3)[i] = fr;
    }
    // one-time pad init + staging pre-zero (upper triangle never rewritten)
    for (int i = ptid; i < TILE_M * S2_32; i += 128) As2[i] = 0u;
    for (int i = ptid; i < 2 * ST_W; i += 128) pb[P_ST + i] = 0u;
    __syncthreads();
    if (ptid < TILE_M) {
        const uint32_t one = packh(__float2half_rn(1.f), __ushort_as_half(0));
        As2[ptid * S2_32 + 50] = one;                 // bias col 100
        uint32_t* rr = As1 + ptid * S1_32;
        rr[12] = one;  rr[LO1 + 12] = 0u;             // bias col 24
        #pragma unroll
        for (int p = 13; p < 16; p++) { rr[p] = 0u; rr[LO1 + p] = 0u; }
    }
    __syncthreads();

    const int ntiles = (B + TILE_M - 1) / TILE_M;
    const int stride = gridDim.x * 4;
    const int tile0  = blockIdx.x * 4 + pipe;

    // ---- pre-loop: load + write X(tile0), then prefetch X(tile0+stride) ----
    float4 px0, px1, px2;
    if (ptid < 2 * TILE_M && tile0 < ntiles) {
        long m = (long)tile0 * TILE_M + (ptid >> 1); if (m >= B) m = B - 1;
        const float4* src = reinterpret_cast<const float4*>(states + m * STATE) + (ptid & 1) * 3;
        px0 = src[0]; px1 = src[1]; px2 = src[2];
        const int row = ptid >> 1, half = ptid & 1;
        uint32_t* rh = As1 + row * S1_32 + half * 6;
        uint32_t h, l;
        split2(px0.x, px0.y, h, l); rh[0] = h; rh[LO1 + 0] = l;
        split2(px0.z, px0.w, h, l); rh[1] = h; rh[LO1 + 1] = l;
        split2(px1.x, px1.y, h, l); rh[2] = h; rh[LO1 + 2] = l;
        split2(px1.z, px1.w, h, l); rh[3] = h; rh[LO1 + 3] = l;
        split2(px2.x, px2.y, h, l); rh[4] = h; rh[LO1 + 4] = l;
        split2(px2.z, px2.w, h, l); rh[5] = h; rh[LO1 + 5] = l;
    }
    PIPE_BAR();
    if (ptid < 2 * TILE_M && tile0 + stride < ntiles) {
        long m = (long)(tile0 + stride) * TILE_M + (ptid >> 1); if (m >= B) m = B - 1;
        const float4* src = reinterpret_cast<const float4*>(states + m * STATE) + (ptid & 1) * 3;
        px0 = src[0]; px1 = src[1]; px2 = src[2];
    }

    int buf = 0;
    for (int tile = tile0; tile < ntiles; tile += stride) {
        float* sChol = reinterpret_cast<float*>(pb + P_ST + buf * ST_W);
        float* sMean = sChol + TILE_M * 36;

        // ---- layer 1: As1 -> As2 (MT1, balanced 7/6) ----
        {
            float c1[7][4];
            wgemm_ldsm<KS1, 7>(As1, S1_32, LO1, Bp1, NT12, nt0, ncnt, wrow, lane, c1);
            epi_relu16<7>(c1, As2, wrow, nt0, ncnt, g, t);
        }
        PIPE_BAR();                                        // S2: hidden1 ready + As1 free

        // ---- write next tile's X into As1 (overlaps layer 2), prefetch next-next ----
        {
            int nxt = tile + stride;
            if (ptid < 2 * TILE_M && nxt < ntiles) {
                const int row = ptid >> 1, half = ptid & 1;
                uint32_t* rh = As1 + row * S1_32 + half * 6;
                uint32_t h, l;
                split2(px0.x, px0.y, h, l); rh[0] = h; rh[LO1 + 0] = l;
                split2(px0.z, px0.w, h, l); rh[1] = h; rh[LO1 + 1] = l;
                split2(px1.x, px1.y, h, l); rh[2] = h; rh[LO1 + 2] = l;
                split2(px1.z, px1.w, h, l); rh[3] = h; rh[LO1 + 3] = l;
                split2(px2.x, px2.y, h, l); rh[4] = h; rh[LO1 + 4] = l;
                split2(px2.z, px2.w, h, l); rh[5] = h; rh[LO1 + 5] = l;
            }
            int nxt2 = tile + 2 * stride;
            if (ptid < 2 * TILE_M && nxt2 < ntiles) {
                long m = (long)nxt2 * TILE_M + (ptid >> 1); if (m >= B) m = B - 1;
                const float4* src = reinterpret_cast<const float4*>(states + m * STATE) + (ptid & 1) * 3;
                px0 = src[0]; px1 = src[1]; px2 = src[2];
            }
        }

        // ---- layer 2: balanced MT2 (B fragments read once; 7/7/6/6 units) ----
        {
            float c2[4][2][4];
            if (w == 0)      wgemm_mt2<KS23, 4, 3, 1>(As2, S2_32, LO2, Bp2, NT12, 0,  lane, c2);
            else if (w == 1) wgemm_mt2<KS23, 4, 2, 3>(As2, S2_32, LO2, Bp2, NT12, 3,  lane, c2);
            else if (w == 2) wgemm_mt2<KS23, 3, 3, 3>(As2, S2_32, LO2, Bp2, NT12, 7,  lane, c2);
            else             wgemm_mt2<KS23, 3, 3, 3>(As2, S2_32, LO2, Bp2, NT12, 10, lane, c2);
            PIPE_BAR();                                    // S3: As2 reads done
            if (w == 0)      epi_mt2<4, 3, 1>(c2, As2, 0,  g, t);
            else if (w == 1) epi_mt2<4, 2, 3>(c2, As2, 3,  g, t);
            else if (w == 2) epi_mt2<3, 3, 3>(c2, As2, 7,  g, t);
            else             epi_mt2<3, 3, 3>(c2, As2, 10, g, t);
        }
        PIPE_BAR();                                        // S4: hidden2 ready

        // ---- head gemm + staged activation scatter ----
        {
            float c3[2][4];
            wgemm_ldsm<KS23, 2>(As2, S2_32, LO2, Bp3, NT3, nt03, 2, wrow3, lane, c3);
            #pragma unroll
            for (int j = 0; j < 2; j++)
                #pragma unroll
                for (int i = 0; i < 4; i++) {
                    int row = wrow3 + g + ((i >= 2) ? 8 : 0);
                    int col = 8 * (nt03 + j) + 2 * t + (i & 1);
                    float v = c3[j][i];
                    if (col < ACT) {
                        sMean[row * ACT + col] = tanhf(v);
                    } else if (col < NHEAD) {
                        float sp = fmaxf(v, 0.f) + log1pf(expf(-fabsf(v)));
                        sChol[row * 36 + c_pos[col - ACT]] = sp;
                    }
                }
        }
        PIPE_BAR();                                        // S5: staged

        // ---- coalesced writeback (double-buffered staging, no trailing bar) ----
        if ((tile + 1) * TILE_M <= B) {
            float4* pm = reinterpret_cast<float4*>(out + (size_t)tile * (TILE_M * ACT));
            const float4* sm4 = reinterpret_cast<const float4*>(sMean);
            for (int i = ptid; i < TILE_M * ACT / 4; i += 128) pm[i] = sm4[i];
            float4* pc = reinterpret_cast<float4*>(out + (size_t)B * ACT + (size_t)tile * (TILE_M * 36));
            const float4* sc4 = reinterpret_cast<const float4*>(sChol);
            for (int i = ptid; i < TILE_M * 36 / 4; i += 128) pc[i] = sc4[i];
        } else {
            int nrow = B - tile * TILE_M;
            for (int i = ptid; i < nrow * ACT; i += 128)
                out[(size_t)tile * (TILE_M * ACT) + i] = sMean[i];
            for (int i = ptid; i < nrow * 36; i += 128)
                out[(size_t)B * ACT + (size_t)tile * (TILE_M * 36) + i] = sChol[i];
        }
        buf ^= 1;
    }
}

extern "C" void kernel_launch(void* const* d_in, const int* in_sizes, int n_in,
                              void* d_out, int out_size)
{
    const float* states = (const float*)d_in[0];
    const float* W1 = (const float*)d_in[1];
    const float* b1 = (const float*)d_in[2];
    const float* W2 = (const float*)d_in[3];
    const float* b2 = (const float*)d_in[4];
    const float* Wm = (const float*)d_in[5];
    const float* bm = (const float*)d_in[6];
    const float* Wc = (const float*)d_in[7];
    const float* bc = (const float*)d_in[8];
    float* out = (float*)d_out;

    const int B = in_sizes[0] / STATE;
    const int ntiles = (B + TILE_M - 1) / TILE_M;
    const size_t smem_bytes = (size_t)F_TOTAL * 4;   // 195072 B

    cudaFuncSetAttribute(actor_mma,
                         cudaFuncAttributeMaxDynamicSharedMemorySize,
                         (int)smem_bytes);

    int nstreams = (ntiles + 3) / 4;
    int grid = nstreams < 152 ? nstreams : 152;      // 1 CTA/SM, 4 pipelines each
    actor_mma<<<grid, TPB, smem_bytes>>>(states, W1, b1, W2, b2,
                                         Wm, bm, Wc, bc, out, B);
}